// round 9
// baseline (speedup 1.0000x reference)
#include <cuda_runtime.h>
#include <cuda_fp16.h>
#include <math.h>
#include <stdint.h>

#define BATCH 1024
#define INF   256
#define OUTF  256
#define NBF   9
#define KD    2304          // NBF * INF; k = n*INF + i
#define NSPLIT 4
#define BK    32
#define IT_PASS  72         // 2304/32
#define IT_SPLIT 18         // 72/4
#define BM 128
#define BN 64
#define NSTAGE 3

// ---- scratch (__device__ globals: allocation-free rule) ----
__device__ __half g_F[(size_t)BATCH * KD];
__device__ __half g_W[(size_t)OUTF * KD];
__device__ float  g_part[NSPLIT][(size_t)BATCH * OUTF];
__device__ unsigned g_cnt[(BATCH / BM) * (OUTF / BN)];   // zero-init; wraps -> self-reset

// ---------------------------------------------------------------------------
// prep_f: cubic B-spline basis + silu -> fp16, 2 elems/thread (512 CTAs).
// K layout k = n*INF + i. Uniform grid (h=0.4): compile-time reciprocals.
// silu via single MUFU.TANH: silu(v) = v*(0.5*tanh(0.5v)+0.5).
// ---------------------------------------------------------------------------
__global__ void prep_f_kernel(const float* __restrict__ x,
                              const float* __restrict__ grid) {
    int t = blockIdx.x * blockDim.x + threadIdx.x;     // 0 .. 131071
    if (t >= BATCH * INF / 2) return;
    int b  = t >> 7;
    int i2 = (t & 127) * 2;
    float2 xv2 = ((const float2*)x)[t];

    float g[12];
#pragma unroll
    for (int j = 0; j < 12; j++) g[j] = __ldg(grid + j);
    const float r1 = 2.5f, r2 = 1.25f, r3 = 0.83333333333f;

    float bas[2][11];
#pragma unroll
    for (int l = 0; l < 2; l++) {
        float v = l ? xv2.y : xv2.x;
#pragma unroll
        for (int j = 0; j < 11; j++)
            bas[l][j] = (v >= g[j] && v < g[j + 1]) ? 1.0f : 0.0f;
#pragma unroll
        for (int j = 0; j < 10; j++)
            bas[l][j] = (v - g[j]) * r1 * bas[l][j] + (g[j + 2] - v) * r1 * bas[l][j + 1];
#pragma unroll
        for (int j = 0; j < 9; j++)
            bas[l][j] = (v - g[j]) * r2 * bas[l][j] + (g[j + 3] - v) * r2 * bas[l][j + 1];
#pragma unroll
        for (int j = 0; j < 8; j++)
            bas[l][j] = (v - g[j]) * r3 * bas[l][j] + (g[j + 4] - v) * r3 * bas[l][j + 1];
        bas[l][7] += (v >= g[8]) ? 1.0f : 0.0f;
        // silu via tanh: sigmoid(v) = 0.5*tanh(0.5v)+0.5  (1 MUFU)
        float th;
        asm("tanh.approx.f32 %0, %1;" : "=f"(th) : "f"(0.5f * v));
        bas[l][8] = v * fmaf(0.5f, th, 0.5f);
    }

    size_t rowb = (size_t)b * KD + i2;
#pragma unroll
    for (int n = 0; n < 9; n++) {
        __half2 hv = __floats2half2_rn(bas[0][n], bas[1][n]);
        *(__half2*)&g_F[rowb + n * INF] = hv;
    }
}

// ---------------------------------------------------------------------------
// prep_w: W[o][n*INF+i] = coeff[o,i,n]*spline_w[o,i] (n<8); [8*INF+i]=base_w.
// ---------------------------------------------------------------------------
__global__ void prep_w_kernel(const float* __restrict__ coeff,
                              const float* __restrict__ base_weight,
                              const float* __restrict__ spline_weight) {
    int t = blockIdx.x * blockDim.x + threadIdx.x;     // 0 .. 32767
    if (t >= OUTF * INF / 2) return;
    int o  = t >> 7;
    int i2 = (t & 127) * 2;

    float2 s2 = ((const float2*)spline_weight)[t];
    float2 bw = ((const float2*)base_weight)[t];
    const float4* c4 = (const float4*)(coeff + ((size_t)o * INF + i2) * 8);
    float4 a0 = c4[0], a1 = c4[1], a2 = c4[2], a3 = c4[3];
    float cv[2][9] = {
        {a0.x * s2.x, a0.y * s2.x, a0.z * s2.x, a0.w * s2.x,
         a1.x * s2.x, a1.y * s2.x, a1.z * s2.x, a1.w * s2.x, bw.x},
        {a2.x * s2.y, a2.y * s2.y, a2.z * s2.y, a2.w * s2.y,
         a3.x * s2.y, a3.y * s2.y, a3.z * s2.y, a3.w * s2.y, bw.y}};

    size_t rowb = (size_t)o * KD + i2;
#pragma unroll
    for (int n = 0; n < 9; n++) {
        __half2 hv = __floats2half2_rn(cv[0][n], cv[1][n]);
        *(__half2*)&g_W[rowb + n * INF] = hv;
    }
}

// ---------------------------------------------------------------------------
// GEMM: C = F * W^T, fp16 in / fp32 accum, K = 2304, split-K z=4.
// mma.sync m16n8k16, BM=128 BN=64, 8 warps (4Mx2N, warp tile 32x32),
// 3-stage cp.async, XOR-swizzled smem, grid (8,4,4) = 128 CTAs.
// Fused deterministic split-K reduction: last CTA per tile sums the 4
// freshly-written (L2-resident) partials in fixed z-order -> out.
// ---------------------------------------------------------------------------
#define A_TILE_B (BM * 64)      // 8192
#define B_TILE_B (BN * 64)      // 4096
#define STAGE_B  (A_TILE_B + B_TILE_B)

#define CP16(dst_u32, src_ptr) \
    asm volatile("cp.async.cg.shared.global [%0], [%1], 16;\n" \
                 :: "r"(dst_u32), "l"(src_ptr))

#define LDMX4(r0,r1,r2,r3, addr) \
    asm volatile("ldmatrix.sync.aligned.m8n8.x4.shared.b16 {%0,%1,%2,%3}, [%4];\n" \
                 : "=r"(r0),"=r"(r1),"=r"(r2),"=r"(r3) : "r"(addr))

#define MMA_F16(d, a, b0_, b1_) \
    asm volatile("mma.sync.aligned.m16n8k16.row.col.f32.f16.f16.f32 " \
                 "{%0,%1,%2,%3},{%4,%5,%6,%7},{%8,%9},{%0,%1,%2,%3};\n" \
                 : "+f"(d[0]),"+f"(d[1]),"+f"(d[2]),"+f"(d[3]) \
                 : "r"(a[0]),"r"(a[1]),"r"(a[2]),"r"(a[3]),"r"(b0_),"r"(b1_))

__global__ __launch_bounds__(256, 1)
void gemm_kernel(float* __restrict__ out) {
    __shared__ __align__(16) uint8_t smem[NSTAGE * STAGE_B];
    __shared__ int s_last;

    const int tid  = threadIdx.x;
    const int warp = tid >> 5;
    const int lane = tid & 31;
    const int bm = blockIdx.x * BM;
    const int bn = blockIdx.y * BN;
    const int z  = blockIdx.z;
    const int wm = (warp >> 1) * 32;    // 0,32,64,96
    const int wn = (warp & 1) * 32;     // 0,32
    const int tileid = blockIdx.x * (OUTF / BN) + blockIdx.y;

    const uint32_t smem_u32 = (uint32_t)__cvta_generic_to_shared(smem);

    auto load_tile = [&](int stage, int it) {
        int k0 = it * BK;
        uint32_t sA = smem_u32 + stage * STAGE_B;
        uint32_t sB = sA + A_TILE_B;
#pragma unroll
        for (int h = 0; h < 2; h++) {           // A: 512 16B chunks
            int slot = tid + h * 256;
            int row = slot >> 2, c = slot & 3;
            const __half* gp = g_F + (size_t)(bm + row) * KD + k0 + c * 8;
            uint32_t d = sA + (uint32_t)((row * 4 + (c ^ ((row >> 1) & 3))) << 4);
            CP16(d, gp);
        }
        {
            int row = tid >> 2, c = tid & 3;    // B: 256 chunks
            const __half* gp = g_W + (size_t)(bn + row) * KD + k0 + c * 8;
            uint32_t d = sB + (uint32_t)((row * 4 + (c ^ ((row >> 1) & 3))) << 4);
            CP16(d, gp);
        }
        asm volatile("cp.async.commit_group;\n" ::);
    };

    float acc[2][4][4];
#pragma unroll
    for (int a = 0; a < 2; a++)
#pragma unroll
        for (int b = 0; b < 4; b++)
#pragma unroll
            for (int c = 0; c < 4; c++) acc[a][b][c] = 0.0f;

    const int it0 = z * IT_SPLIT;
    load_tile(0, it0);
    load_tile(1, it0 + 1);

    for (int t = 0; t < IT_SPLIT; t++) {
        int nx = t + NSTAGE - 1;
        if (nx < IT_SPLIT) load_tile((t + 2) % NSTAGE, it0 + nx);
        else asm volatile("cp.async.commit_group;\n" ::);
        asm volatile("cp.async.wait_group 2;\n" ::);
        __syncthreads();

        int stage = t % NSTAGE;
        uint32_t aBase = smem_u32 + stage * STAGE_B;
        uint32_t bBase = aBase + A_TILE_B;

#pragma unroll
        for (int kk = 0; kk < 2; kk++) {
            uint32_t afr[2][4];
#pragma unroll
            for (int mt = 0; mt < 2; mt++) {
                int row = wm + mt * 16 + (lane & 15);
                int ch  = kk * 2 + (lane >> 4);
                uint32_t ad = aBase + (uint32_t)((row * 4 + (ch ^ ((row >> 1) & 3))) << 4);
                LDMX4(afr[mt][0], afr[mt][1], afr[mt][2], afr[mt][3], ad);
            }
            uint32_t bfr[2][4];
#pragma unroll
            for (int nh = 0; nh < 2; nh++) {
                int row = wn + nh * 16 + ((lane >> 4) << 3) + (lane & 7);
                int ch  = kk * 2 + ((lane >> 3) & 1);
                uint32_t ad = bBase + (uint32_t)((row * 4 + (ch ^ ((row >> 1) & 3))) << 4);
                LDMX4(bfr[nh][0], bfr[nh][1], bfr[nh][2], bfr[nh][3], ad);
            }
#pragma unroll
            for (int mt = 0; mt < 2; mt++)
#pragma unroll
                for (int nt = 0; nt < 4; nt++) {
                    uint32_t b0 = bfr[nt >> 1][(nt & 1) * 2];
                    uint32_t b1 = bfr[nt >> 1][(nt & 1) * 2 + 1];
                    MMA_F16(acc[mt][nt], afr[mt], b0, b1);
                }
        }
        __syncthreads();
    }

    // ---- write split-K partial ----
    float* P = &g_part[z][0];
    const int g2 = lane >> 2, tg = lane & 3;
#pragma unroll
    for (int mt = 0; mt < 2; mt++)
#pragma unroll
        for (int nt = 0; nt < 4; nt++) {
            int r  = bm + wm + mt * 16 + g2;
            int cc = bn + wn + nt * 8 + tg * 2;
            *(float2*)&P[(size_t)r * OUTF + cc] =
                make_float2(acc[mt][nt][0], acc[mt][nt][1]);
            *(float2*)&P[(size_t)(r + 8) * OUTF + cc] =
                make_float2(acc[mt][nt][2], acc[mt][nt][3]);
        }

    // ---- fused serialized split-K reduction (deterministic z-order) ----
    __threadfence();              // make this CTA's partial visible
    __syncthreads();              // all threads fenced before the count
    if (tid == 0) {
        unsigned old = atomicInc(&g_cnt[tileid], NSPLIT - 1);   // wraps 3 -> 0
        s_last = (old == NSPLIT - 1);
    }
    __syncthreads();
    if (s_last) {
        __threadfence();          // acquire side
        // tile region: BM x BN floats = 2048 float4 slots; 8 per thread
#pragma unroll
        for (int j = 0; j < (BM * BN / 4) / 256; j++) {
            int idx = tid + j * 256;
            int r   = idx >> 4;                  // 0..127
            int c4  = idx & 15;                  // 0..15
            size_t off = ((size_t)(bm + r) * OUTF + bn) / 4 + c4;
            float4 s0 = __ldcg((const float4*)&g_part[0][0] + off);
            float4 s1 = __ldcg((const float4*)&g_part[1][0] + off);
            float4 s2 = __ldcg((const float4*)&g_part[2][0] + off);
            float4 s3 = __ldcg((const float4*)&g_part[3][0] + off);
            float4 rr;
            rr.x = (s0.x + s1.x) + (s2.x + s3.x);
            rr.y = (s0.y + s1.y) + (s2.y + s3.y);
            rr.z = (s0.z + s1.z) + (s2.z + s3.z);
            rr.w = (s0.w + s1.w) + (s2.w + s3.w);
            ((float4*)out)[off] = rr;
        }
    }
}

// ---------------------------------------------------------------------------
extern "C" void kernel_launch(void* const* d_in, const int* in_sizes, int n_in,
                              void* d_out, int out_size) {
    const float* x             = (const float*)d_in[0];
    const float* grid          = (const float*)d_in[1];
    const float* coeff         = (const float*)d_in[2];
    const float* base_weight   = (const float*)d_in[3];
    const float* spline_weight = (const float*)d_in[4];
    float* out = (float*)d_out;

    prep_f_kernel<<<(BATCH * INF / 2 + 255) / 256, 256>>>(x, grid);
    prep_w_kernel<<<(OUTF * INF / 2 + 255) / 256, 256>>>(coeff, base_weight, spline_weight);

    dim3 g(BATCH / BM, OUTF / BN, NSPLIT);
    gemm_kernel<<<g, 256>>>(out);
}

// round 10
// speedup vs baseline: 1.1235x; 1.1235x over previous
#include <cuda_runtime.h>
#include <cuda_fp16.h>
#include <math.h>
#include <stdint.h>

#define BATCH 1024
#define INF   256
#define OUTF  256
#define NBF   9
#define KD    2304          // NBF * INF; k = n*INF + i
#define NSPLIT 4
#define BK    32
#define IT_SPLIT 18         // 72/4
#define BM 128
#define BN 64
#define NSTAGE 3

// ---- scratch (__device__ globals: allocation-free rule) ----
__device__ __half g_F[(size_t)BATCH * KD];
__device__ __half g_W[(size_t)OUTF * KD];
__device__ float  g_part[NSPLIT][(size_t)BATCH * OUTF];

// ---------------------------------------------------------------------------
// prep_f: CLOSED-FORM uniform cubic B-spline + silu -> fp16, 4 elems/thread.
// Only 4 bases are nonzero at any x: interval j = floor((x-g0)/h), local u.
//   w0=(1-u)^3/6, w1=(3u^3-6u^2+4)/6, w2=(-3u^3+3u^2+3u+1)/6, w3=u^3/6
// map to basis indices j-3..j (clipped to 0..7); + reference tail
//   bas[7] += (x >= g[8]).  Out-of-range x -> all weights 0.
// silu via single MUFU.TANH. K layout k = n*INF + i (coalesced stores).
// ---------------------------------------------------------------------------
__global__ void prep_f_kernel(const float* __restrict__ x,
                              const float* __restrict__ grid) {
    int t = blockIdx.x * blockDim.x + threadIdx.x;     // 0 .. 65535
    if (t >= BATCH * INF / 4) return;
    int b  = t >> 6;
    int i4 = (t & 63) * 4;
    float4 xv4 = ((const float4*)x)[t];
    float xv[4] = {xv4.x, xv4.y, xv4.z, xv4.w};

    const float g0  = __ldg(grid + 0);      // -2.2
    const float g8  = __ldg(grid + 8);      //  1.0
    const float rh  = 2.5f;                 // 1/h, h = 0.4
    const float c16 = 1.0f / 6.0f;

    float w[4][4];     // [elem][w0..w3]
    int   jj[4];
    float si[4];
#pragma unroll
    for (int l = 0; l < 4; l++) {
        float v  = xv[l];
        float tp = (v - g0) * rh;
        float jf = floorf(tp);
        float u  = tp - jf;
        int   j  = (int)jf;
        bool valid = (j >= 0) && (j <= 10);
        float u2 = u * u, u3 = u2 * u;
        float omu = 1.0f - u;
        float w0 = omu * omu * omu * c16;
        float w1 = fmaf(3.0f, u3, fmaf(-6.0f, u2, 4.0f)) * c16;
        float w2 = fmaf(-3.0f, u3, fmaf(3.0f, u2, fmaf(3.0f, u, 1.0f))) * c16;
        float w3 = u3 * c16;
        w[l][0] = valid ? w0 : 0.0f;
        w[l][1] = valid ? w1 : 0.0f;
        w[l][2] = valid ? w2 : 0.0f;
        w[l][3] = valid ? w3 : 0.0f;
        jj[l] = j;
        float th;
        asm("tanh.approx.f32 %0, %1;" : "=f"(th) : "f"(0.5f * v));
        si[l] = v * fmaf(0.5f, th, 0.5f);
    }

    size_t rowb = (size_t)b * KD + i4;
#pragma unroll
    for (int n = 0; n < 8; n++) {
        float val[4];
#pragma unroll
        for (int l = 0; l < 4; l++) {
            int d = jj[l] - n;      // basis n holds w[3-d] when 0<=d<=3
            float r = 0.0f;
            r = (d == 3) ? w[l][0] : r;
            r = (d == 2) ? w[l][1] : r;
            r = (d == 1) ? w[l][2] : r;
            r = (d == 0) ? w[l][3] : r;
            if (n == 7) r += (xv[l] >= g8) ? 1.0f : 0.0f;
            val[l] = r;
        }
        __half2 h0 = __floats2half2_rn(val[0], val[1]);
        __half2 h1 = __floats2half2_rn(val[2], val[3]);
        uint2 hp;
        hp.x = *(uint32_t*)&h0; hp.y = *(uint32_t*)&h1;
        *(uint2*)&g_F[rowb + n * INF] = hp;
    }
    {   // silu slot
        __half2 h0 = __floats2half2_rn(si[0], si[1]);
        __half2 h1 = __floats2half2_rn(si[2], si[3]);
        uint2 hp;
        hp.x = *(uint32_t*)&h0; hp.y = *(uint32_t*)&h1;
        *(uint2*)&g_F[rowb + 8 * INF] = hp;
    }
}

// ---------------------------------------------------------------------------
// prep_w: W[o][n*INF+i] = coeff[o,i,n]*spline_w[o,i] (n<8); [8*INF+i]=base_w.
// ---------------------------------------------------------------------------
__global__ void prep_w_kernel(const float* __restrict__ coeff,
                              const float* __restrict__ base_weight,
                              const float* __restrict__ spline_weight) {
    int t = blockIdx.x * blockDim.x + threadIdx.x;     // 0 .. 32767
    if (t >= OUTF * INF / 2) return;
    int o  = t >> 7;
    int i2 = (t & 127) * 2;

    float2 s2 = ((const float2*)spline_weight)[t];
    float2 bw = ((const float2*)base_weight)[t];
    const float4* c4 = (const float4*)(coeff + ((size_t)o * INF + i2) * 8);
    float4 a0 = c4[0], a1 = c4[1], a2 = c4[2], a3 = c4[3];
    float cv[2][9] = {
        {a0.x * s2.x, a0.y * s2.x, a0.z * s2.x, a0.w * s2.x,
         a1.x * s2.x, a1.y * s2.x, a1.z * s2.x, a1.w * s2.x, bw.x},
        {a2.x * s2.y, a2.y * s2.y, a2.z * s2.y, a2.w * s2.y,
         a3.x * s2.y, a3.y * s2.y, a3.z * s2.y, a3.w * s2.y, bw.y}};

    size_t rowb = (size_t)o * KD + i2;
#pragma unroll
    for (int n = 0; n < 9; n++) {
        __half2 hv = __floats2half2_rn(cv[0][n], cv[1][n]);
        *(__half2*)&g_W[rowb + n * INF] = hv;
    }
}

// ---------------------------------------------------------------------------
// GEMM: C = F * W^T, fp16 in / fp32 accum, K = 2304, split-K z=4 (R7 config).
// mma.sync m16n8k16, BM=128 BN=64, 8 warps (4Mx2N), 3-stage cp.async,
// XOR-swizzled smem, grid (8,4,4) = 128 CTAs.
// ---------------------------------------------------------------------------
#define A_TILE_B (BM * 64)      // 8192
#define B_TILE_B (BN * 64)      // 4096
#define STAGE_B  (A_TILE_B + B_TILE_B)

#define CP16(dst_u32, src_ptr) \
    asm volatile("cp.async.cg.shared.global [%0], [%1], 16;\n" \
                 :: "r"(dst_u32), "l"(src_ptr))

#define LDMX4(r0,r1,r2,r3, addr) \
    asm volatile("ldmatrix.sync.aligned.m8n8.x4.shared.b16 {%0,%1,%2,%3}, [%4];\n" \
                 : "=r"(r0),"=r"(r1),"=r"(r2),"=r"(r3) : "r"(addr))

#define MMA_F16(d, a, b0_, b1_) \
    asm volatile("mma.sync.aligned.m16n8k16.row.col.f32.f16.f16.f32 " \
                 "{%0,%1,%2,%3},{%4,%5,%6,%7},{%8,%9},{%0,%1,%2,%3};\n" \
                 : "+f"(d[0]),"+f"(d[1]),"+f"(d[2]),"+f"(d[3]) \
                 : "r"(a[0]),"r"(a[1]),"r"(a[2]),"r"(a[3]),"r"(b0_),"r"(b1_))

__global__ __launch_bounds__(256, 1)
void gemm_kernel() {
    __shared__ __align__(16) uint8_t smem[NSTAGE * STAGE_B];

    const int tid  = threadIdx.x;
    const int warp = tid >> 5;
    const int lane = tid & 31;
    const int bm = blockIdx.x * BM;
    const int bn = blockIdx.y * BN;
    const int z  = blockIdx.z;
    const int wm = (warp >> 1) * 32;
    const int wn = (warp & 1) * 32;

    const uint32_t smem_u32 = (uint32_t)__cvta_generic_to_shared(smem);

    auto load_tile = [&](int stage, int it) {
        int k0 = it * BK;
        uint32_t sA = smem_u32 + stage * STAGE_B;
        uint32_t sB = sA + A_TILE_B;
#pragma unroll
        for (int h = 0; h < 2; h++) {           // A: 512 16B chunks
            int slot = tid + h * 256;
            int row = slot >> 2, c = slot & 3;
            const __half* gp = g_F + (size_t)(bm + row) * KD + k0 + c * 8;
            uint32_t d = sA + (uint32_t)((row * 4 + (c ^ ((row >> 1) & 3))) << 4);
            CP16(d, gp);
        }
        {
            int row = tid >> 2, c = tid & 3;    // B: 256 chunks
            const __half* gp = g_W + (size_t)(bn + row) * KD + k0 + c * 8;
            uint32_t d = sB + (uint32_t)((row * 4 + (c ^ ((row >> 1) & 3))) << 4);
            CP16(d, gp);
        }
        asm volatile("cp.async.commit_group;\n" ::);
    };

    float acc[2][4][4];
#pragma unroll
    for (int a = 0; a < 2; a++)
#pragma unroll
        for (int b = 0; b < 4; b++)
#pragma unroll
            for (int c = 0; c < 4; c++) acc[a][b][c] = 0.0f;

    const int it0 = z * IT_SPLIT;
    load_tile(0, it0);
    load_tile(1, it0 + 1);

    for (int t = 0; t < IT_SPLIT; t++) {
        int nx = t + NSTAGE - 1;
        if (nx < IT_SPLIT) load_tile((t + 2) % NSTAGE, it0 + nx);
        else asm volatile("cp.async.commit_group;\n" ::);
        asm volatile("cp.async.wait_group 2;\n" ::);
        __syncthreads();

        int stage = t % NSTAGE;
        uint32_t aBase = smem_u32 + stage * STAGE_B;
        uint32_t bBase = aBase + A_TILE_B;

#pragma unroll
        for (int kk = 0; kk < 2; kk++) {
            uint32_t afr[2][4];
#pragma unroll
            for (int mt = 0; mt < 2; mt++) {
                int row = wm + mt * 16 + (lane & 15);
                int ch  = kk * 2 + (lane >> 4);
                uint32_t ad = aBase + (uint32_t)((row * 4 + (ch ^ ((row >> 1) & 3))) << 4);
                LDMX4(afr[mt][0], afr[mt][1], afr[mt][2], afr[mt][3], ad);
            }
            uint32_t bfr[2][4];
#pragma unroll
            for (int nh = 0; nh < 2; nh++) {
                int row = wn + nh * 16 + ((lane >> 4) << 3) + (lane & 7);
                int ch  = kk * 2 + ((lane >> 3) & 1);
                uint32_t ad = bBase + (uint32_t)((row * 4 + (ch ^ ((row >> 1) & 3))) << 4);
                LDMX4(bfr[nh][0], bfr[nh][1], bfr[nh][2], bfr[nh][3], ad);
            }
#pragma unroll
            for (int mt = 0; mt < 2; mt++)
#pragma unroll
                for (int nt = 0; nt < 4; nt++) {
                    uint32_t b0 = bfr[nt >> 1][(nt & 1) * 2];
                    uint32_t b1 = bfr[nt >> 1][(nt & 1) * 2 + 1];
                    MMA_F16(acc[mt][nt], afr[mt], b0, b1);
                }
        }
        __syncthreads();
    }

    // ---- write split-K partial ----
    float* P = &g_part[z][0];
    const int g2 = lane >> 2, tg = lane & 3;
#pragma unroll
    for (int mt = 0; mt < 2; mt++)
#pragma unroll
        for (int nt = 0; nt < 4; nt++) {
            int r  = bm + wm + mt * 16 + g2;
            int cc = bn + wn + nt * 8 + tg * 2;
            *(float2*)&P[(size_t)r * OUTF + cc] =
                make_float2(acc[mt][nt][0], acc[mt][nt][1]);
            *(float2*)&P[(size_t)(r + 8) * OUTF + cc] =
                make_float2(acc[mt][nt][2], acc[mt][nt][3]);
        }
}

// ---------------------------------------------------------------------------
// reduce: 256 CTAs x 256 thr, 1 float4/thread, 4 front-batched ldcg,
// fixed summation order (deterministic).
// ---------------------------------------------------------------------------
__global__ void reduce_kernel(float* __restrict__ out) {
    int idx = blockIdx.x * blockDim.x + threadIdx.x;   // float4 slot
    float4 s0 = __ldcg((const float4*)&g_part[0][0] + idx);
    float4 s1 = __ldcg((const float4*)&g_part[1][0] + idx);
    float4 s2 = __ldcg((const float4*)&g_part[2][0] + idx);
    float4 s3 = __ldcg((const float4*)&g_part[3][0] + idx);
    float4 r;
    r.x = (s0.x + s1.x) + (s2.x + s3.x);
    r.y = (s0.y + s1.y) + (s2.y + s3.y);
    r.z = (s0.z + s1.z) + (s2.z + s3.z);
    r.w = (s0.w + s1.w) + (s2.w + s3.w);
    ((float4*)out)[idx] = r;
}

// ---------------------------------------------------------------------------
extern "C" void kernel_launch(void* const* d_in, const int* in_sizes, int n_in,
                              void* d_out, int out_size) {
    const float* x             = (const float*)d_in[0];
    const float* grid          = (const float*)d_in[1];
    const float* coeff         = (const float*)d_in[2];
    const float* base_weight   = (const float*)d_in[3];
    const float* spline_weight = (const float*)d_in[4];
    float* out = (float*)d_out;

    prep_f_kernel<<<(BATCH * INF / 4 + 255) / 256, 256>>>(x, grid);
    prep_w_kernel<<<(OUTF * INF / 2 + 255) / 256, 256>>>(coeff, base_weight, spline_weight);

    dim3 g(BATCH / BM, OUTF / BN, NSPLIT);
    gemm_kernel<<<g, 256>>>();

    reduce_kernel<<<(BATCH * OUTF / 4) / 256, 256>>>(out);
}

// round 11
// speedup vs baseline: 1.2183x; 1.0844x over previous
#include <cuda_runtime.h>
#include <cuda_fp16.h>
#include <math.h>
#include <stdint.h>

#define BATCH 1024
#define INF   256
#define OUTF  256
#define NBF   9
#define KD    2304          // NBF * INF; k = n*INF + i
#define NSPLIT 4
#define BK    32
#define IT_SPLIT 18         // 72/4
#define BM 128
#define BN 64
#define NSTAGE 3

// ---- scratch (__device__ globals: allocation-free rule) ----
__device__ __half g_F[(size_t)BATCH * KD];
__device__ __half g_W[(size_t)OUTF * KD];

// ---------------------------------------------------------------------------
// prep_f: cubic B-spline basis + silu -> fp16, 4 elems/thread (R7 version).
// K layout k = n*INF + i; 4 adjacent i -> 8-byte packed stores.
// Uniform grid (h = 0.4): denominators are compile-time reciprocals.
// ---------------------------------------------------------------------------
__global__ void prep_f_kernel(const float* __restrict__ x,
                              const float* __restrict__ grid) {
    int t = blockIdx.x * blockDim.x + threadIdx.x;     // 0 .. 65535
    if (t >= BATCH * INF / 4) return;
    int b  = t >> 6;
    int i4 = (t & 63) * 4;
    float4 xv4 = ((const float4*)x)[t];
    float xv[4] = {xv4.x, xv4.y, xv4.z, xv4.w};

    float g[12];
#pragma unroll
    for (int j = 0; j < 12; j++) g[j] = __ldg(grid + j);
    const float r1 = 2.5f, r2 = 1.25f, r3 = 0.83333333333f;

    float bas[4][11];
#pragma unroll
    for (int l = 0; l < 4; l++) {
        float v = xv[l];
#pragma unroll
        for (int j = 0; j < 11; j++)
            bas[l][j] = (v >= g[j] && v < g[j + 1]) ? 1.0f : 0.0f;
#pragma unroll
        for (int j = 0; j < 10; j++)
            bas[l][j] = (v - g[j]) * r1 * bas[l][j] + (g[j + 2] - v) * r1 * bas[l][j + 1];
#pragma unroll
        for (int j = 0; j < 9; j++)
            bas[l][j] = (v - g[j]) * r2 * bas[l][j] + (g[j + 3] - v) * r2 * bas[l][j + 1];
#pragma unroll
        for (int j = 0; j < 8; j++)
            bas[l][j] = (v - g[j]) * r3 * bas[l][j] + (g[j + 4] - v) * r3 * bas[l][j + 1];
        bas[l][7] += (v >= g[8]) ? 1.0f : 0.0f;
        bas[l][8] = __fdividef(v, 1.0f + __expf(-v));   // silu in slot 8
    }

    size_t rowb = (size_t)b * KD + i4;
#pragma unroll
    for (int n = 0; n < 9; n++) {
        __half2 h0 = __floats2half2_rn(bas[0][n], bas[1][n]);
        __half2 h1 = __floats2half2_rn(bas[2][n], bas[3][n]);
        uint2 hp;
        hp.x = *(uint32_t*)&h0; hp.y = *(uint32_t*)&h1;
        *(uint2*)&g_F[rowb + n * INF] = hp;
    }
}

// ---------------------------------------------------------------------------
// prep_w: W[o][n*INF+i] = coeff[o,i,n]*spline_w[o,i] (n<8); [8*INF+i]=base_w.
// ---------------------------------------------------------------------------
__global__ void prep_w_kernel(const float* __restrict__ coeff,
                              const float* __restrict__ base_weight,
                              const float* __restrict__ spline_weight) {
    int t = blockIdx.x * blockDim.x + threadIdx.x;     // 0 .. 32767
    if (t >= OUTF * INF / 2) return;
    int o  = t >> 7;
    int i2 = (t & 127) * 2;

    float2 s2 = ((const float2*)spline_weight)[t];
    float2 bw = ((const float2*)base_weight)[t];
    const float4* c4 = (const float4*)(coeff + ((size_t)o * INF + i2) * 8);
    float4 a0 = c4[0], a1 = c4[1], a2 = c4[2], a3 = c4[3];
    float cv[2][9] = {
        {a0.x * s2.x, a0.y * s2.x, a0.z * s2.x, a0.w * s2.x,
         a1.x * s2.x, a1.y * s2.x, a1.z * s2.x, a1.w * s2.x, bw.x},
        {a2.x * s2.y, a2.y * s2.y, a2.z * s2.y, a2.w * s2.y,
         a3.x * s2.y, a3.y * s2.y, a3.z * s2.y, a3.w * s2.y, bw.y}};

    size_t rowb = (size_t)o * KD + i2;
#pragma unroll
    for (int n = 0; n < 9; n++) {
        __half2 hv = __floats2half2_rn(cv[0][n], cv[1][n]);
        *(__half2*)&g_W[rowb + n * INF] = hv;
    }
}

// ---------------------------------------------------------------------------
// GEMM: C = F * W^T, fp16 in / fp32 accum, K = 2304, split-K z=4.
// mma.sync m16n8k16, BM=128 BN=64, 8 warps (4Mx2N), 3-stage cp.async,
// XOR-swizzled smem, grid (8,4,4) = 128 CTAs, cluster (1,1,4): the four
// z-siblings of each tile reduce through DSMEM (fixed z order, no gmem
// partials, no reduce kernel). Smem acc reuses the dead pipeline buffers.
// ---------------------------------------------------------------------------
#define A_TILE_B (BM * 64)      // 8192
#define B_TILE_B (BN * 64)      // 4096
#define STAGE_B  (A_TILE_B + B_TILE_B)
#define SMEM_BYTES (NSTAGE * STAGE_B)       // 36864 >= BM*BN*4 = 32768

#define CP16(dst_u32, src_ptr) \
    asm volatile("cp.async.cg.shared.global [%0], [%1], 16;\n" \
                 :: "r"(dst_u32), "l"(src_ptr))

#define LDMX4(r0,r1,r2,r3, addr) \
    asm volatile("ldmatrix.sync.aligned.m8n8.x4.shared.b16 {%0,%1,%2,%3}, [%4];\n" \
                 : "=r"(r0),"=r"(r1),"=r"(r2),"=r"(r3) : "r"(addr))

#define MMA_F16(d, a, b0_, b1_) \
    asm volatile("mma.sync.aligned.m16n8k16.row.col.f32.f16.f16.f32 " \
                 "{%0,%1,%2,%3},{%4,%5,%6,%7},{%8,%9},{%0,%1,%2,%3};\n" \
                 : "+f"(d[0]),"+f"(d[1]),"+f"(d[2]),"+f"(d[3]) \
                 : "r"(a[0]),"r"(a[1]),"r"(a[2]),"r"(a[3]),"r"(b0_),"r"(b1_))

#define CLUSTER_ARRIVE() asm volatile("barrier.cluster.arrive.aligned;" ::: "memory")
#define CLUSTER_WAIT()   asm volatile("barrier.cluster.wait.aligned;"   ::: "memory")

__device__ __forceinline__ uint32_t mapa_rank(uint32_t addr, uint32_t rank) {
    uint32_t r;
    asm("mapa.shared::cluster.u32 %0, %1, %2;" : "=r"(r) : "r"(addr), "r"(rank));
    return r;
}
__device__ __forceinline__ float4 ld_dsmem_f4(uint32_t addr) {
    float4 v;
    asm volatile("ld.shared::cluster.v4.f32 {%0,%1,%2,%3}, [%4];"
                 : "=f"(v.x), "=f"(v.y), "=f"(v.z), "=f"(v.w) : "r"(addr));
    return v;
}

__global__ __launch_bounds__(256, 1) __cluster_dims__(1, 1, NSPLIT)
void gemm_kernel(float* __restrict__ out) {
    __shared__ __align__(16) uint8_t smem[SMEM_BYTES];

    const int tid  = threadIdx.x;
    const int warp = tid >> 5;
    const int lane = tid & 31;
    const int bm = blockIdx.x * BM;
    const int bn = blockIdx.y * BN;
    const int z  = blockIdx.z;           // == cluster rank (dims 1,1,4)
    const int wm = (warp >> 1) * 32;
    const int wn = (warp & 1) * 32;

    const uint32_t smem_u32 = (uint32_t)__cvta_generic_to_shared(smem);

    auto load_tile = [&](int stage, int it) {
        int k0 = it * BK;
        uint32_t sA = smem_u32 + stage * STAGE_B;
        uint32_t sB = sA + A_TILE_B;
#pragma unroll
        for (int h = 0; h < 2; h++) {           // A: 512 16B chunks
            int slot = tid + h * 256;
            int row = slot >> 2, c = slot & 3;
            const __half* gp = g_F + (size_t)(bm + row) * KD + k0 + c * 8;
            uint32_t d = sA + (uint32_t)((row * 4 + (c ^ ((row >> 1) & 3))) << 4);
            CP16(d, gp);
        }
        {
            int row = tid >> 2, c = tid & 3;    // B: 256 chunks
            const __half* gp = g_W + (size_t)(bn + row) * KD + k0 + c * 8;
            uint32_t d = sB + (uint32_t)((row * 4 + (c ^ ((row >> 1) & 3))) << 4);
            CP16(d, gp);
        }
        asm volatile("cp.async.commit_group;\n" ::);
    };

    float acc[2][4][4];
#pragma unroll
    for (int a = 0; a < 2; a++)
#pragma unroll
        for (int b = 0; b < 4; b++)
#pragma unroll
            for (int c = 0; c < 4; c++) acc[a][b][c] = 0.0f;

    const int it0 = z * IT_SPLIT;
    load_tile(0, it0);
    load_tile(1, it0 + 1);

    for (int t = 0; t < IT_SPLIT; t++) {
        int nx = t + NSTAGE - 1;
        if (nx < IT_SPLIT) load_tile((t + 2) % NSTAGE, it0 + nx);
        else asm volatile("cp.async.commit_group;\n" ::);
        asm volatile("cp.async.wait_group 2;\n" ::);
        __syncthreads();

        int stage = t % NSTAGE;
        uint32_t aBase = smem_u32 + stage * STAGE_B;
        uint32_t bBase = aBase + A_TILE_B;

#pragma unroll
        for (int kk = 0; kk < 2; kk++) {
            uint32_t afr[2][4];
#pragma unroll
            for (int mt = 0; mt < 2; mt++) {
                int row = wm + mt * 16 + (lane & 15);
                int ch  = kk * 2 + (lane >> 4);
                uint32_t ad = aBase + (uint32_t)((row * 4 + (ch ^ ((row >> 1) & 3))) << 4);
                LDMX4(afr[mt][0], afr[mt][1], afr[mt][2], afr[mt][3], ad);
            }
            uint32_t bfr[2][4];
#pragma unroll
            for (int nh = 0; nh < 2; nh++) {
                int row = wn + nh * 16 + ((lane >> 4) << 3) + (lane & 7);
                int ch  = kk * 2 + ((lane >> 3) & 1);
                uint32_t ad = bBase + (uint32_t)((row * 4 + (ch ^ ((row >> 1) & 3))) << 4);
                LDMX4(bfr[nh][0], bfr[nh][1], bfr[nh][2], bfr[nh][3], ad);
            }
#pragma unroll
            for (int mt = 0; mt < 2; mt++)
#pragma unroll
                for (int nt = 0; nt < 4; nt++) {
                    uint32_t b0 = bfr[nt >> 1][(nt & 1) * 2];
                    uint32_t b1 = bfr[nt >> 1][(nt & 1) * 2 + 1];
                    MMA_F16(acc[mt][nt], afr[mt], b0, b1);
                }
        }
        __syncthreads();
    }

    // ---- stash partial in smem (pipeline buffers are dead now) ----
    // layout: float acc_s[BM][BN] at smem offset 0
    float* accS = (float*)smem;
    const int g2 = lane >> 2, tg = lane & 3;
#pragma unroll
    for (int mt = 0; mt < 2; mt++)
#pragma unroll
        for (int nt = 0; nt < 4; nt++) {
            int r  = wm + mt * 16 + g2;
            int cc = wn + nt * 8 + tg * 2;
            *(float2*)&accS[r * BN + cc] =
                make_float2(acc[mt][nt][0], acc[mt][nt][1]);
            *(float2*)&accS[(r + 8) * BN + cc] =
                make_float2(acc[mt][nt][2], acc[mt][nt][3]);
        }
    __syncthreads();

    // ---- cluster-wide DSMEM reduction, fixed z order (deterministic) ----
    CLUSTER_ARRIVE();            // release: accS visible to cluster peers
    CLUSTER_WAIT();

    // this CTA reduces rows [z*32, z*32+32) of the tile: 512 float4 slots
#pragma unroll
    for (int j = 0; j < 2; j++) {
        int slot = tid + j * 256;            // 0..511
        int r    = z * 32 + (slot >> 4);     // tile row
        int c4   = slot & 15;                // float4 col
        uint32_t off = smem_u32 + (uint32_t)((r * BN + c4 * 4) * 4);
        float4 s0 = ld_dsmem_f4(mapa_rank(off, 0));
        float4 s1 = ld_dsmem_f4(mapa_rank(off, 1));
        float4 s2 = ld_dsmem_f4(mapa_rank(off, 2));
        float4 s3 = ld_dsmem_f4(mapa_rank(off, 3));
        float4 rr;
        rr.x = (s0.x + s1.x) + (s2.x + s3.x);
        rr.y = (s0.y + s1.y) + (s2.y + s3.y);
        rr.z = (s0.z + s1.z) + (s2.z + s3.z);
        rr.w = (s0.w + s1.w) + (s2.w + s3.w);
        *(float4*)&out[(size_t)(bm + r) * OUTF + bn + c4 * 4] = rr;
    }

    // keep smem alive until all peers finished reading
    CLUSTER_ARRIVE();
    CLUSTER_WAIT();
}

// ---------------------------------------------------------------------------
extern "C" void kernel_launch(void* const* d_in, const int* in_sizes, int n_in,
                              void* d_out, int out_size) {
    const float* x             = (const float*)d_in[0];
    const float* grid          = (const float*)d_in[1];
    const float* coeff         = (const float*)d_in[2];
    const float* base_weight   = (const float*)d_in[3];
    const float* spline_weight = (const float*)d_in[4];
    float* out = (float*)d_out;

    prep_f_kernel<<<(BATCH * INF / 4 + 255) / 256, 256>>>(x, grid);
    prep_w_kernel<<<(OUTF * INF / 2 + 255) / 256, 256>>>(coeff, base_weight, spline_weight);

    dim3 g(BATCH / BM, OUTF / BN, NSPLIT);
    gemm_kernel<<<g, 256>>>(out);
}

// round 12
// speedup vs baseline: 1.2411x; 1.0187x over previous
#include <cuda_runtime.h>
#include <cuda_fp16.h>
#include <math.h>
#include <stdint.h>

#define BATCH 1024
#define INF   256
#define OUTF  256
#define NBF   9
#define KD    2304          // NBF * INF; k = n*INF + i
#define NSPLIT 4
#define BK    32
#define IT_SPLIT 18         // 72/4
#define BM 128
#define BN 64
#define NSTAGE 3

// ---- scratch (__device__ globals: allocation-free rule) ----
__device__ __half g_F[(size_t)BATCH * KD];
__device__ __half g_W[(size_t)OUTF * KD];
__device__ float  g_part[NSPLIT][(size_t)BATCH * OUTF];

// ---------------------------------------------------------------------------
// prep_f: CLOSED-FORM uniform cubic B-spline + silu via smem scatter.
// One CTA per batch row; thread i owns element (b, i).
//  - zero own smem column s[0..8][i]            (column-local, no race)
//  - j = floor((x-g0)*2.5), u = frac; 4 cubic weights; scatter to s[j-d][i]
//  - tail: s[7][i] += (x >= grid[8])
//  - silu -> s[8][i]
//  - one __syncthreads, then coalesced fp32->fp16 copyout (k = n*INF + i).
// Weights are C2-continuous at knots -> floor() boundary ambiguity is a
// ~1e-7 perturbation (validated in R10: identical rel_err).
// ---------------------------------------------------------------------------
__global__ __launch_bounds__(256, 8)
void prep_f_kernel(const float* __restrict__ x,
                   const float* __restrict__ grid) {
    __shared__ float s[NBF][INF + 4];     // 9 x 260 floats, row-pad 16B

    const int b = blockIdx.x;
    const int i = threadIdx.x;
    const float v  = x[b * INF + i];
    const float g0 = __ldg(grid + 0);     // -2.2
    const float g8 = __ldg(grid + 8);     //  1.0
    const float c16 = 1.0f / 6.0f;

    // zero own column
#pragma unroll
    for (int n = 0; n < NBF; n++) s[n][i] = 0.0f;

    // closed-form cubic weights
    float tp = (v - g0) * 2.5f;           // 1/h, h = 0.4
    float jf = floorf(tp);
    float u  = tp - jf;
    int   j  = (int)jf;
    if (j >= 0 && j <= 10) {
        float u2 = u * u, u3 = u2 * u, omu = 1.0f - u;
        float w0 = omu * omu * omu * c16;                                  // d=3
        float w1 = fmaf(3.0f, u3, fmaf(-6.0f, u2, 4.0f)) * c16;            // d=2
        float w2 = fmaf(-3.0f, u3, fmaf(3.0f, u2, fmaf(3.0f, u, 1.0f))) * c16; // d=1
        float w3 = u3 * c16;                                               // d=0
        if (j     <= 7)            s[j    ][i] = w3;
        if (j - 1 >= 0 && j - 1 <= 7) s[j - 1][i] = w2;
        if (j - 2 >= 0 && j - 2 <= 7) s[j - 2][i] = w1;
        if (j - 3 >= 0)            s[j - 3][i] = w0;   // j-3 <= 7 always (j<=10)
    }
    if (v >= g8) s[7][i] += 1.0f;         // reference tail: bases[:,-1] += ...

    // silu in slot 8
    s[8][i] = __fdividef(v, 1.0f + __expf(-v));
    __syncthreads();

    // copyout: 9 x 256 floats = 576 float4 -> fp16 uint2, coalesced
    size_t rowb = (size_t)b * KD;
    for (int slot = i; slot < 576; slot += 256) {
        int n = slot >> 6;                // 64 float4 per row
        int c = slot & 63;
        float4 f = *(const float4*)&s[n][c * 4];
        __half2 h0 = __floats2half2_rn(f.x, f.y);
        __half2 h1 = __floats2half2_rn(f.z, f.w);
        uint2 hp;
        hp.x = *(uint32_t*)&h0; hp.y = *(uint32_t*)&h1;
        *(uint2*)&g_F[rowb + n * INF + c * 4] = hp;
    }
}

// ---------------------------------------------------------------------------
// prep_w: W[o][n*INF+i] = coeff[o,i,n]*spline_w[o,i] (n<8); [8*INF+i]=base_w.
// ---------------------------------------------------------------------------
__global__ void prep_w_kernel(const float* __restrict__ coeff,
                              const float* __restrict__ base_weight,
                              const float* __restrict__ spline_weight) {
    int t = blockIdx.x * blockDim.x + threadIdx.x;     // 0 .. 32767
    if (t >= OUTF * INF / 2) return;
    int o  = t >> 7;
    int i2 = (t & 127) * 2;

    float2 s2 = ((const float2*)spline_weight)[t];
    float2 bw = ((const float2*)base_weight)[t];
    const float4* c4 = (const float4*)(coeff + ((size_t)o * INF + i2) * 8);
    float4 a0 = c4[0], a1 = c4[1], a2 = c4[2], a3 = c4[3];
    float cv[2][9] = {
        {a0.x * s2.x, a0.y * s2.x, a0.z * s2.x, a0.w * s2.x,
         a1.x * s2.x, a1.y * s2.x, a1.z * s2.x, a1.w * s2.x, bw.x},
        {a2.x * s2.y, a2.y * s2.y, a2.z * s2.y, a2.w * s2.y,
         a3.x * s2.y, a3.y * s2.y, a3.z * s2.y, a3.w * s2.y, bw.y}};

    size_t rowb = (size_t)o * KD + i2;
#pragma unroll
    for (int n = 0; n < 9; n++) {
        __half2 hv = __floats2half2_rn(cv[0][n], cv[1][n]);
        *(__half2*)&g_W[rowb + n * INF] = hv;
    }
}

// ---------------------------------------------------------------------------
// GEMM: C = F * W^T, fp16 in / fp32 accum, K = 2304, split-K z=4 (R7 config).
// mma.sync m16n8k16, BM=128 BN=64, 8 warps (4Mx2N), 3-stage cp.async,
// XOR-swizzled smem, grid (8,4,4) = 128 CTAs.
// ---------------------------------------------------------------------------
#define A_TILE_B (BM * 64)      // 8192
#define B_TILE_B (BN * 64)      // 4096
#define STAGE_B  (A_TILE_B + B_TILE_B)

#define CP16(dst_u32, src_ptr) \
    asm volatile("cp.async.cg.shared.global [%0], [%1], 16;\n" \
                 :: "r"(dst_u32), "l"(src_ptr))

#define LDMX4(r0,r1,r2,r3, addr) \
    asm volatile("ldmatrix.sync.aligned.m8n8.x4.shared.b16 {%0,%1,%2,%3}, [%4];\n" \
                 : "=r"(r0),"=r"(r1),"=r"(r2),"=r"(r3) : "r"(addr))

#define MMA_F16(d, a, b0_, b1_) \
    asm volatile("mma.sync.aligned.m16n8k16.row.col.f32.f16.f16.f32 " \
                 "{%0,%1,%2,%3},{%4,%5,%6,%7},{%8,%9},{%0,%1,%2,%3};\n" \
                 : "+f"(d[0]),"+f"(d[1]),"+f"(d[2]),"+f"(d[3]) \
                 : "r"(a[0]),"r"(a[1]),"r"(a[2]),"r"(a[3]),"r"(b0_),"r"(b1_))

__global__ __launch_bounds__(256, 1)
void gemm_kernel() {
    __shared__ __align__(16) uint8_t smem[NSTAGE * STAGE_B];

    const int tid  = threadIdx.x;
    const int warp = tid >> 5;
    const int lane = tid & 31;
    const int bm = blockIdx.x * BM;
    const int bn = blockIdx.y * BN;
    const int z  = blockIdx.z;
    const int wm = (warp >> 1) * 32;
    const int wn = (warp & 1) * 32;

    const uint32_t smem_u32 = (uint32_t)__cvta_generic_to_shared(smem);

    auto load_tile = [&](int stage, int it) {
        int k0 = it * BK;
        uint32_t sA = smem_u32 + stage * STAGE_B;
        uint32_t sB = sA + A_TILE_B;
#pragma unroll
        for (int h = 0; h < 2; h++) {           // A: 512 16B chunks
            int slot = tid + h * 256;
            int row = slot >> 2, c = slot & 3;
            const __half* gp = g_F + (size_t)(bm + row) * KD + k0 + c * 8;
            uint32_t d = sA + (uint32_t)((row * 4 + (c ^ ((row >> 1) & 3))) << 4);
            CP16(d, gp);
        }
        {
            int row = tid >> 2, c = tid & 3;    // B: 256 chunks
            const __half* gp = g_W + (size_t)(bn + row) * KD + k0 + c * 8;
            uint32_t d = sB + (uint32_t)((row * 4 + (c ^ ((row >> 1) & 3))) << 4);
            CP16(d, gp);
        }
        asm volatile("cp.async.commit_group;\n" ::);
    };

    float acc[2][4][4];
#pragma unroll
    for (int a = 0; a < 2; a++)
#pragma unroll
        for (int b = 0; b < 4; b++)
#pragma unroll
            for (int c = 0; c < 4; c++) acc[a][b][c] = 0.0f;

    const int it0 = z * IT_SPLIT;
    load_tile(0, it0);
    load_tile(1, it0 + 1);

    for (int t = 0; t < IT_SPLIT; t++) {
        int nx = t + NSTAGE - 1;
        if (nx < IT_SPLIT) load_tile((t + 2) % NSTAGE, it0 + nx);
        else asm volatile("cp.async.commit_group;\n" ::);
        asm volatile("cp.async.wait_group 2;\n" ::);
        __syncthreads();

        int stage = t % NSTAGE;
        uint32_t aBase = smem_u32 + stage * STAGE_B;
        uint32_t bBase = aBase + A_TILE_B;

#pragma unroll
        for (int kk = 0; kk < 2; kk++) {
            uint32_t afr[2][4];
#pragma unroll
            for (int mt = 0; mt < 2; mt++) {
                int row = wm + mt * 16 + (lane & 15);
                int ch  = kk * 2 + (lane >> 4);
                uint32_t ad = aBase + (uint32_t)((row * 4 + (ch ^ ((row >> 1) & 3))) << 4);
                LDMX4(afr[mt][0], afr[mt][1], afr[mt][2], afr[mt][3], ad);
            }
            uint32_t bfr[2][4];
#pragma unroll
            for (int nh = 0; nh < 2; nh++) {
                int row = wn + nh * 16 + ((lane >> 4) << 3) + (lane & 7);
                int ch  = kk * 2 + ((lane >> 3) & 1);
                uint32_t ad = bBase + (uint32_t)((row * 4 + (ch ^ ((row >> 1) & 3))) << 4);
                LDMX4(bfr[nh][0], bfr[nh][1], bfr[nh][2], bfr[nh][3], ad);
            }
#pragma unroll
            for (int mt = 0; mt < 2; mt++)
#pragma unroll
                for (int nt = 0; nt < 4; nt++) {
                    uint32_t b0 = bfr[nt >> 1][(nt & 1) * 2];
                    uint32_t b1 = bfr[nt >> 1][(nt & 1) * 2 + 1];
                    MMA_F16(acc[mt][nt], afr[mt], b0, b1);
                }
        }
        __syncthreads();
    }

    // ---- write split-K partial ----
    float* P = &g_part[z][0];
    const int g2 = lane >> 2, tg = lane & 3;
#pragma unroll
    for (int mt = 0; mt < 2; mt++)
#pragma unroll
        for (int nt = 0; nt < 4; nt++) {
            int r  = bm + wm + mt * 16 + g2;
            int cc = bn + wn + nt * 8 + tg * 2;
            *(float2*)&P[(size_t)r * OUTF + cc] =
                make_float2(acc[mt][nt][0], acc[mt][nt][1]);
            *(float2*)&P[(size_t)(r + 8) * OUTF + cc] =
                make_float2(acc[mt][nt][2], acc[mt][nt][3]);
        }
}

// ---------------------------------------------------------------------------
// reduce: 256 CTAs x 256 thr, 1 float4/thread, 4 front-batched ldcg,
// fixed summation order (deterministic).
// ---------------------------------------------------------------------------
__global__ void reduce_kernel(float* __restrict__ out) {
    int idx = blockIdx.x * blockDim.x + threadIdx.x;   // float4 slot
    float4 s0 = __ldcg((const float4*)&g_part[0][0] + idx);
    float4 s1 = __ldcg((const float4*)&g_part[1][0] + idx);
    float4 s2 = __ldcg((const float4*)&g_part[2][0] + idx);
    float4 s3 = __ldcg((const float4*)&g_part[3][0] + idx);
    float4 r;
    r.x = (s0.x + s1.x) + (s2.x + s3.x);
    r.y = (s0.y + s1.y) + (s2.y + s3.y);
    r.z = (s0.z + s1.z) + (s2.z + s3.z);
    r.w = (s0.w + s1.w) + (s2.w + s3.w);
    ((float4*)out)[idx] = r;
}

// ---------------------------------------------------------------------------
extern "C" void kernel_launch(void* const* d_in, const int* in_sizes, int n_in,
                              void* d_out, int out_size) {
    const float* x             = (const float*)d_in[0];
    const float* grid          = (const float*)d_in[1];
    const float* coeff         = (const float*)d_in[2];
    const float* base_weight   = (const float*)d_in[3];
    const float* spline_weight = (const float*)d_in[4];
    float* out = (float*)d_out;

    prep_f_kernel<<<BATCH, 256>>>(x, grid);
    prep_w_kernel<<<(OUTF * INF / 2 + 255) / 256, 256>>>(coeff, base_weight, spline_weight);

    dim3 g(BATCH / BM, OUTF / BN, NSPLIT);
    gemm_kernel<<<g, 256>>>();

    reduce_kernel<<<(BATCH * OUTF / 4) / 256, 256>>>(out);
}

// round 14
// speedup vs baseline: 1.3833x; 1.1146x over previous
#include <cuda_runtime.h>
#include <cuda_fp16.h>
#include <math.h>
#include <stdint.h>

#define BATCH 1024
#define INF   256
#define OUTF  256
#define NBF   9
#define KD    2304          // NBF * INF; k = n*INF + i
#define NSPLIT 4
#define BK    32
#define IT_SPLIT 18         // 72/4
#define BM 128
#define BN 64
#define NSTAGE 3

// ---- scratch (__device__ globals: allocation-free rule) ----
__device__ __half g_F[(size_t)BATCH * KD];
__device__ __half g_W[(size_t)OUTF * KD];

// ---------------------------------------------------------------------------
// prep_all: ONE launch does everything before the GEMM.
//   blocks [0,1024)      : prep_f (closed-form B-spline scatter, 1 CTA/row)
//   blocks [1024,1152)   : prep_w
//   blocks [1152,1408)   : zero out[] (65536 float4, exactly 1 per thread)
// ---------------------------------------------------------------------------
__global__ __launch_bounds__(256, 8)
void prep_all_kernel(const float* __restrict__ x,
                     const float* __restrict__ grid,
                     const float* __restrict__ coeff,
                     const float* __restrict__ base_weight,
                     const float* __restrict__ spline_weight,
                     float* __restrict__ out) {
    const int blk = blockIdx.x;
    const int tid = threadIdx.x;

    if (blk < BATCH) {
        // ---------------- prep_f: closed-form cubic B-spline + silu --------
        __shared__ float s[NBF][INF + 4];
        const int b = blk, i = tid;
        const float v  = x[b * INF + i];
        const float g0 = __ldg(grid + 0);
        const float g8 = __ldg(grid + 8);
        const float c16 = 1.0f / 6.0f;

#pragma unroll
        for (int n = 0; n < NBF; n++) s[n][i] = 0.0f;

        float tp = (v - g0) * 2.5f;       // 1/h, h = 0.4
        float jf = floorf(tp);
        float u  = tp - jf;
        int   j  = (int)jf;
        if (j >= 0 && j <= 10) {
            float u2 = u * u, u3 = u2 * u, omu = 1.0f - u;
            float w0 = omu * omu * omu * c16;
            float w1 = fmaf(3.0f, u3, fmaf(-6.0f, u2, 4.0f)) * c16;
            float w2 = fmaf(-3.0f, u3, fmaf(3.0f, u2, fmaf(3.0f, u, 1.0f))) * c16;
            float w3 = u3 * c16;
            if (j     <= 7)               s[j    ][i] = w3;
            if (j - 1 >= 0 && j - 1 <= 7) s[j - 1][i] = w2;
            if (j - 2 >= 0 && j - 2 <= 7) s[j - 2][i] = w1;
            if (j - 3 >= 0)               s[j - 3][i] = w0;
        }
        if (v >= g8) s[7][i] += 1.0f;     // reference tail
        s[8][i] = __fdividef(v, 1.0f + __expf(-v));   // silu
        __syncthreads();

        size_t rowb = (size_t)b * KD;
        for (int slot = i; slot < 576; slot += 256) {
            int n = slot >> 6, c = slot & 63;
            float4 f = *(const float4*)&s[n][c * 4];
            __half2 h0 = __floats2half2_rn(f.x, f.y);
            __half2 h1 = __floats2half2_rn(f.z, f.w);
            uint2 hp;
            hp.x = *(uint32_t*)&h0; hp.y = *(uint32_t*)&h1;
            *(uint2*)&g_F[rowb + n * INF + c * 4] = hp;
        }
    } else if (blk < BATCH + 128) {
        // ---------------- prep_w -------------------------------------------
        int t = (blk - BATCH) * 256 + tid;            // 0 .. 32767
        int o  = t >> 7;
        int i2 = (t & 127) * 2;
        float2 s2 = ((const float2*)spline_weight)[t];
        float2 bw = ((const float2*)base_weight)[t];
        const float4* c4 = (const float4*)(coeff + ((size_t)o * INF + i2) * 8);
        float4 a0 = c4[0], a1 = c4[1], a2 = c4[2], a3 = c4[3];
        float cv[2][9] = {
            {a0.x * s2.x, a0.y * s2.x, a0.z * s2.x, a0.w * s2.x,
             a1.x * s2.x, a1.y * s2.x, a1.z * s2.x, a1.w * s2.x, bw.x},
            {a2.x * s2.y, a2.y * s2.y, a2.z * s2.y, a2.w * s2.y,
             a3.x * s2.y, a3.y * s2.y, a3.z * s2.y, a3.w * s2.y, bw.y}};
        size_t rowb = (size_t)o * KD + i2;
#pragma unroll
        for (int n = 0; n < 9; n++) {
            __half2 hv = __floats2half2_rn(cv[0][n], cv[1][n]);
            *(__half2*)&g_W[rowb + n * INF] = hv;
        }
    } else {
        // ---------------- zero out[]: 256 CTAs x 256 thr x 1 float4 -------
        int slot = (blk - BATCH - 128) * 256 + tid;   // 0 .. 65535 (all slots)
        ((float4*)out)[slot] = make_float4(0.f, 0.f, 0.f, 0.f);
    }
}

// ---------------------------------------------------------------------------
// GEMM: out += F * W^T (fp16 in / fp32 accum), K = 2304, split-K z=4.
// mma.sync m16n8k16, BM=128 BN=64, 8 warps (4Mx2N), 3-stage cp.async,
// XOR-swizzled smem, grid (8,4,4) = 128 CTAs.
// Epilogue: restage tile in smem, then red.global.add.v4.f32 into out
// (out pre-zeroed by launch #1, stream-ordered before this kernel).
// ---------------------------------------------------------------------------
#define A_TILE_B (BM * 64)      // 8192
#define B_TILE_B (BN * 64)      // 4096
#define STAGE_B  (A_TILE_B + B_TILE_B)
#define SMEM_BYTES (NSTAGE * STAGE_B)   // 36864 >= BM*BN*4 = 32768

#define CP16(dst_u32, src_ptr) \
    asm volatile("cp.async.cg.shared.global [%0], [%1], 16;\n" \
                 :: "r"(dst_u32), "l"(src_ptr))

#define LDMX4(r0,r1,r2,r3, addr) \
    asm volatile("ldmatrix.sync.aligned.m8n8.x4.shared.b16 {%0,%1,%2,%3}, [%4];\n" \
                 : "=r"(r0),"=r"(r1),"=r"(r2),"=r"(r3) : "r"(addr))

#define MMA_F16(d, a, b0_, b1_) \
    asm volatile("mma.sync.aligned.m16n8k16.row.col.f32.f16.f16.f32 " \
                 "{%0,%1,%2,%3},{%4,%5,%6,%7},{%8,%9},{%0,%1,%2,%3};\n" \
                 : "+f"(d[0]),"+f"(d[1]),"+f"(d[2]),"+f"(d[3]) \
                 : "r"(a[0]),"r"(a[1]),"r"(a[2]),"r"(a[3]),"r"(b0_),"r"(b1_))

#define REDV4(ptr, v) \
    asm volatile("red.global.add.v4.f32 [%0], {%1, %2, %3, %4};\n" \
                 :: "l"(ptr), "f"((v).x), "f"((v).y), "f"((v).z), "f"((v).w) \
                 : "memory")

__global__ __launch_bounds__(256, 1)
void gemm_kernel(float* __restrict__ out) {
    __shared__ __align__(16) uint8_t smem[SMEM_BYTES];

    const int tid  = threadIdx.x;
    const int warp = tid >> 5;
    const int lane = tid & 31;
    const int bm = blockIdx.x * BM;
    const int bn = blockIdx.y * BN;
    const int z  = blockIdx.z;
    const int wm = (warp >> 1) * 32;
    const int wn = (warp & 1) * 32;

    const uint32_t smem_u32 = (uint32_t)__cvta_generic_to_shared(smem);

    auto load_tile = [&](int stage, int it) {
        int k0 = it * BK;
        uint32_t sA = smem_u32 + stage * STAGE_B;
        uint32_t sB = sA + A_TILE_B;
#pragma unroll
        for (int h = 0; h < 2; h++) {           // A: 512 16B chunks
            int slot = tid + h * 256;
            int row = slot >> 2, c = slot & 3;
            const __half* gp = g_F + (size_t)(bm + row) * KD + k0 + c * 8;
            uint32_t d = sA + (uint32_t)((row * 4 + (c ^ ((row >> 1) & 3))) << 4);
            CP16(d, gp);
        }
        {
            int row = tid >> 2, c = tid & 3;    // B: 256 chunks
            const __half* gp = g_W + (size_t)(bn + row) * KD + k0 + c * 8;
            uint32_t d = sB + (uint32_t)((row * 4 + (c ^ ((row >> 1) & 3))) << 4);
            CP16(d, gp);
        }
        asm volatile("cp.async.commit_group;\n" ::);
    };

    float acc[2][4][4];
#pragma unroll
    for (int a = 0; a < 2; a++)
#pragma unroll
        for (int b = 0; b < 4; b++)
#pragma unroll
            for (int c = 0; c < 4; c++) acc[a][b][c] = 0.0f;

    const int it0 = z * IT_SPLIT;
    load_tile(0, it0);
    load_tile(1, it0 + 1);

    for (int t = 0; t < IT_SPLIT; t++) {
        int nx = t + NSTAGE - 1;
        if (nx < IT_SPLIT) load_tile((t + 2) % NSTAGE, it0 + nx);
        else asm volatile("cp.async.commit_group;\n" ::);
        asm volatile("cp.async.wait_group 2;\n" ::);
        __syncthreads();

        int stage = t % NSTAGE;
        uint32_t aBase = smem_u32 + stage * STAGE_B;
        uint32_t bBase = aBase + A_TILE_B;

#pragma unroll
        for (int kk = 0; kk < 2; kk++) {
            uint32_t afr[2][4];
#pragma unroll
            for (int mt = 0; mt < 2; mt++) {
                int row = wm + mt * 16 + (lane & 15);
                int ch  = kk * 2 + (lane >> 4);
                uint32_t ad = aBase + (uint32_t)((row * 4 + (ch ^ ((row >> 1) & 3))) << 4);
                LDMX4(afr[mt][0], afr[mt][1], afr[mt][2], afr[mt][3], ad);
            }
            uint32_t bfr[2][4];
#pragma unroll
            for (int nh = 0; nh < 2; nh++) {
                int row = wn + nh * 16 + ((lane >> 4) << 3) + (lane & 7);
                int ch  = kk * 2 + ((lane >> 3) & 1);
                uint32_t ad = bBase + (uint32_t)((row * 4 + (ch ^ ((row >> 1) & 3))) << 4);
                LDMX4(bfr[nh][0], bfr[nh][1], bfr[nh][2], bfr[nh][3], ad);
            }
#pragma unroll
            for (int mt = 0; mt < 2; mt++)
#pragma unroll
                for (int nt = 0; nt < 4; nt++) {
                    uint32_t b0 = bfr[nt >> 1][(nt & 1) * 2];
                    uint32_t b1 = bfr[nt >> 1][(nt & 1) * 2 + 1];
                    MMA_F16(acc[mt][nt], afr[mt], b0, b1);
                }
        }
        __syncthreads();
    }

    // ---- epilogue: restage tile in smem (pipeline buffers dead) ----------
    float* accS = (float*)smem;
    const int g2 = lane >> 2, tg = lane & 3;
#pragma unroll
    for (int mt = 0; mt < 2; mt++)
#pragma unroll
        for (int nt = 0; nt < 4; nt++) {
            int r  = wm + mt * 16 + g2;
            int cc = wn + nt * 8 + tg * 2;
            *(float2*)&accS[r * BN + cc] =
                make_float2(acc[mt][nt][0], acc[mt][nt][1]);
            *(float2*)&accS[(r + 8) * BN + cc] =
                make_float2(acc[mt][nt][2], acc[mt][nt][3]);
        }
    __syncthreads();

    // ---- vector-RED accumulate into out (pre-zeroed) ---------------------
#pragma unroll
    for (int j = 0; j < (BM * BN / 4) / 256; j++) {   // 8 float4 per thread
        int slot = tid + j * 256;
        int r    = slot >> 4;                 // 0..127
        int c4   = slot & 15;                 // 0..15
        float4 v = *(const float4*)&accS[r * BN + c4 * 4];
        float* dst = &out[(size_t)(bm + r) * OUTF + bn + c4 * 4];
        REDV4(dst, v);
    }
}

// ---------------------------------------------------------------------------
extern "C" void kernel_launch(void* const* d_in, const int* in_sizes, int n_in,
                              void* d_out, int out_size) {
    const float* x             = (const float*)d_in[0];
    const float* grid          = (const float*)d_in[1];
    const float* coeff         = (const float*)d_in[2];
    const float* base_weight   = (const float*)d_in[3];
    const float* spline_weight = (const float*)d_in[4];
    float* out = (float*)d_out;

    prep_all_kernel<<<BATCH + 128 + 256, 256>>>(x, grid, coeff, base_weight,
                                                spline_weight, out);

    dim3 g(BATCH / BM, OUTF / BN, NSPLIT);
    gemm_kernel<<<g, 256>>>(out);
}

// round 15
// speedup vs baseline: 1.4341x; 1.0367x over previous
#include <cuda_runtime.h>
#include <cuda_fp16.h>
#include <math.h>
#include <stdint.h>

#define BATCH 1024
#define INF   256
#define OUTF  256
#define NBF   9
#define KD    2304          // NBF * INF; k = n*INF + i
#define NSPLIT 8
#define BK    32
#define IT_SPLIT 9          // 72/8
#define BM 128
#define BN 64
#define NSTAGE 3

// ---- scratch (__device__ globals: allocation-free rule) ----
__device__ __half g_F[(size_t)BATCH * KD];
__device__ __half g_W[(size_t)OUTF * KD];

// ---------------------------------------------------------------------------
// prep_all: ONE launch does everything before the GEMM.
//   blocks [0,1024)      : prep_f (closed-form B-spline scatter, 1 CTA/row)
//   blocks [1024,1152)   : prep_w
//   blocks [1152,1408)   : zero out[] (65536 float4, exactly 1 per thread)
// ---------------------------------------------------------------------------
__global__ __launch_bounds__(256, 8)
void prep_all_kernel(const float* __restrict__ x,
                     const float* __restrict__ grid,
                     const float* __restrict__ coeff,
                     const float* __restrict__ base_weight,
                     const float* __restrict__ spline_weight,
                     float* __restrict__ out) {
    const int blk = blockIdx.x;
    const int tid = threadIdx.x;

    if (blk < BATCH) {
        // ---------------- prep_f: closed-form cubic B-spline + silu --------
        __shared__ float s[NBF][INF + 4];
        const int b = blk, i = tid;
        const float v  = x[b * INF + i];
        const float g0 = __ldg(grid + 0);
        const float g8 = __ldg(grid + 8);
        const float c16 = 1.0f / 6.0f;

#pragma unroll
        for (int n = 0; n < NBF; n++) s[n][i] = 0.0f;

        float tp = (v - g0) * 2.5f;       // 1/h, h = 0.4
        float jf = floorf(tp);
        float u  = tp - jf;
        int   j  = (int)jf;
        if (j >= 0 && j <= 10) {
            float u2 = u * u, u3 = u2 * u, omu = 1.0f - u;
            float w0 = omu * omu * omu * c16;
            float w1 = fmaf(3.0f, u3, fmaf(-6.0f, u2, 4.0f)) * c16;
            float w2 = fmaf(-3.0f, u3, fmaf(3.0f, u2, fmaf(3.0f, u, 1.0f))) * c16;
            float w3 = u3 * c16;
            if (j     <= 7)               s[j    ][i] = w3;
            if (j - 1 >= 0 && j - 1 <= 7) s[j - 1][i] = w2;
            if (j - 2 >= 0 && j - 2 <= 7) s[j - 2][i] = w1;
            if (j - 3 >= 0)               s[j - 3][i] = w0;
        }
        if (v >= g8) s[7][i] += 1.0f;     // reference tail
        s[8][i] = __fdividef(v, 1.0f + __expf(-v));   // silu
        __syncthreads();

        size_t rowb = (size_t)b * KD;
        for (int slot = i; slot < 576; slot += 256) {
            int n = slot >> 6, c = slot & 63;
            float4 f = *(const float4*)&s[n][c * 4];
            __half2 h0 = __floats2half2_rn(f.x, f.y);
            __half2 h1 = __floats2half2_rn(f.z, f.w);
            uint2 hp;
            hp.x = *(uint32_t*)&h0; hp.y = *(uint32_t*)&h1;
            *(uint2*)&g_F[rowb + n * INF + c * 4] = hp;
        }
    } else if (blk < BATCH + 128) {
        // ---------------- prep_w -------------------------------------------
        int t = (blk - BATCH) * 256 + tid;            // 0 .. 32767
        int o  = t >> 7;
        int i2 = (t & 127) * 2;
        float2 s2 = ((const float2*)spline_weight)[t];
        float2 bw = ((const float2*)base_weight)[t];
        const float4* c4 = (const float4*)(coeff + ((size_t)o * INF + i2) * 8);
        float4 a0 = c4[0], a1 = c4[1], a2 = c4[2], a3 = c4[3];
        float cv[2][9] = {
            {a0.x * s2.x, a0.y * s2.x, a0.z * s2.x, a0.w * s2.x,
             a1.x * s2.x, a1.y * s2.x, a1.z * s2.x, a1.w * s2.x, bw.x},
            {a2.x * s2.y, a2.y * s2.y, a2.z * s2.y, a2.w * s2.y,
             a3.x * s2.y, a3.y * s2.y, a3.z * s2.y, a3.w * s2.y, bw.y}};
        size_t rowb = (size_t)o * KD + i2;
#pragma unroll
        for (int n = 0; n < 9; n++) {
            __half2 hv = __floats2half2_rn(cv[0][n], cv[1][n]);
            *(__half2*)&g_W[rowb + n * INF] = hv;
        }
    } else {
        // ---------------- zero out[]: 256 CTAs x 256 thr x 1 float4 -------
        int slot = (blk - BATCH - 128) * 256 + tid;   // 0 .. 65535 (all slots)
        ((float4*)out)[slot] = make_float4(0.f, 0.f, 0.f, 0.f);
    }
}

// ---------------------------------------------------------------------------
// GEMM: out += F * W^T (fp16 in / fp32 accum), K = 2304, split-K z=8.
// mma.sync m16n8k16, BM=128 BN=64, 8 warps (4Mx2N), 3-stage cp.async,
// XOR-swizzled smem, grid (8,4,8) = 256 CTAs = 2 CTAs/SM (occupancy 2:
// co-resident CTAs interleave around each other's barriers/loads).
// Epilogue: restage tile in smem, then red.global.add.v4.f32 into out.
// ---------------------------------------------------------------------------
#define A_TILE_B (BM * 64)      // 8192
#define B_TILE_B (BN * 64)      // 4096
#define STAGE_B  (A_TILE_B + B_TILE_B)
#define SMEM_BYTES (NSTAGE * STAGE_B)   // 36864 >= BM*BN*4 = 32768

#define CP16(dst_u32, src_ptr) \
    asm volatile("cp.async.cg.shared.global [%0], [%1], 16;\n" \
                 :: "r"(dst_u32), "l"(src_ptr))

#define LDMX4(r0,r1,r2,r3, addr) \
    asm volatile("ldmatrix.sync.aligned.m8n8.x4.shared.b16 {%0,%1,%2,%3}, [%4];\n" \
                 : "=r"(r0),"=r"(r1),"=r"(r2),"=r"(r3) : "r"(addr))

#define MMA_F16(d, a, b0_, b1_) \
    asm volatile("mma.sync.aligned.m16n8k16.row.col.f32.f16.f16.f32 " \
                 "{%0,%1,%2,%3},{%4,%5,%6,%7},{%8,%9},{%0,%1,%2,%3};\n" \
                 : "+f"(d[0]),"+f"(d[1]),"+f"(d[2]),"+f"(d[3]) \
                 : "r"(a[0]),"r"(a[1]),"r"(a[2]),"r"(a[3]),"r"(b0_),"r"(b1_))

#define REDV4(ptr, v) \
    asm volatile("red.global.add.v4.f32 [%0], {%1, %2, %3, %4};\n" \
                 :: "l"(ptr), "f"((v).x), "f"((v).y), "f"((v).z), "f"((v).w) \
                 : "memory")

__global__ __launch_bounds__(256, 2)
void gemm_kernel(float* __restrict__ out) {
    __shared__ __align__(16) uint8_t smem[SMEM_BYTES];

    const int tid  = threadIdx.x;
    const int warp = tid >> 5;
    const int lane = tid & 31;
    const int bm = blockIdx.x * BM;
    const int bn = blockIdx.y * BN;
    const int z  = blockIdx.z;
    const int wm = (warp >> 1) * 32;
    const int wn = (warp & 1) * 32;

    const uint32_t smem_u32 = (uint32_t)__cvta_generic_to_shared(smem);

    auto load_tile = [&](int stage, int it) {
        int k0 = it * BK;
        uint32_t sA = smem_u32 + stage * STAGE_B;
        uint32_t sB = sA + A_TILE_B;
#pragma unroll
        for (int h = 0; h < 2; h++) {           // A: 512 16B chunks
            int slot = tid + h * 256;
            int row = slot >> 2, c = slot & 3;
            const __half* gp = g_F + (size_t)(bm + row) * KD + k0 + c * 8;
            uint32_t d = sA + (uint32_t)((row * 4 + (c ^ ((row >> 1) & 3))) << 4);
            CP16(d, gp);
        }
        {
            int row = tid >> 2, c = tid & 3;    // B: 256 chunks
            const __half* gp = g_W + (size_t)(bn + row) * KD + k0 + c * 8;
            uint32_t d = sB + (uint32_t)((row * 4 + (c ^ ((row >> 1) & 3))) << 4);
            CP16(d, gp);
        }
        asm volatile("cp.async.commit_group;\n" ::);
    };

    float acc[2][4][4];
#pragma unroll
    for (int a = 0; a < 2; a++)
#pragma unroll
        for (int b = 0; b < 4; b++)
#pragma unroll
            for (int c = 0; c < 4; c++) acc[a][b][c] = 0.0f;

    const int it0 = z * IT_SPLIT;
    load_tile(0, it0);
    load_tile(1, it0 + 1);

    for (int t = 0; t < IT_SPLIT; t++) {
        int nx = t + NSTAGE - 1;
        if (nx < IT_SPLIT) load_tile((t + 2) % NSTAGE, it0 + nx);
        else asm volatile("cp.async.commit_group;\n" ::);
        asm volatile("cp.async.wait_group 2;\n" ::);
        __syncthreads();

        int stage = t % NSTAGE;
        uint32_t aBase = smem_u32 + stage * STAGE_B;
        uint32_t bBase = aBase + A_TILE_B;

#pragma unroll
        for (int kk = 0; kk < 2; kk++) {
            uint32_t afr[2][4];
#pragma unroll
            for (int mt = 0; mt < 2; mt++) {
                int row = wm + mt * 16 + (lane & 15);
                int ch  = kk * 2 + (lane >> 4);
                uint32_t ad = aBase + (uint32_t)((row * 4 + (ch ^ ((row >> 1) & 3))) << 4);
                LDMX4(afr[mt][0], afr[mt][1], afr[mt][2], afr[mt][3], ad);
            }
            uint32_t bfr[2][4];
#pragma unroll
            for (int nh = 0; nh < 2; nh++) {
                int row = wn + nh * 16 + ((lane >> 4) << 3) + (lane & 7);
                int ch  = kk * 2 + ((lane >> 3) & 1);
                uint32_t ad = bBase + (uint32_t)((row * 4 + (ch ^ ((row >> 1) & 3))) << 4);
                LDMX4(bfr[nh][0], bfr[nh][1], bfr[nh][2], bfr[nh][3], ad);
            }
#pragma unroll
            for (int mt = 0; mt < 2; mt++)
#pragma unroll
                for (int nt = 0; nt < 4; nt++) {
                    uint32_t b0 = bfr[nt >> 1][(nt & 1) * 2];
                    uint32_t b1 = bfr[nt >> 1][(nt & 1) * 2 + 1];
                    MMA_F16(acc[mt][nt], afr[mt], b0, b1);
                }
        }
        __syncthreads();
    }

    // ---- epilogue: restage tile in smem (pipeline buffers dead) ----------
    float* accS = (float*)smem;
    const int g2 = lane >> 2, tg = lane & 3;
#pragma unroll
    for (int mt = 0; mt < 2; mt++)
#pragma unroll
        for (int nt = 0; nt < 4; nt++) {
            int r  = wm + mt * 16 + g2;
            int cc = wn + nt * 8 + tg * 2;
            *(float2*)&accS[r * BN + cc] =
                make_float2(acc[mt][nt][0], acc[mt][nt][1]);
            *(float2*)&accS[(r + 8) * BN + cc] =
                make_float2(acc[mt][nt][2], acc[mt][nt][3]);
        }
    __syncthreads();

    // ---- vector-RED accumulate into out (pre-zeroed) ---------------------
#pragma unroll
    for (int j = 0; j < (BM * BN / 4) / 256; j++) {   // 8 float4 per thread
        int slot = tid + j * 256;
        int r    = slot >> 4;                 // 0..127
        int c4   = slot & 15;                 // 0..15
        float4 v = *(const float4*)&accS[r * BN + c4 * 4];
        float* dst = &out[(size_t)(bm + r) * OUTF + bn + c4 * 4];
        REDV4(dst, v);
    }
}

// ---------------------------------------------------------------------------
extern "C" void kernel_launch(void* const* d_in, const int* in_sizes, int n_in,
                              void* d_out, int out_size) {
    const float* x             = (const float*)d_in[0];
    const float* grid          = (const float*)d_in[1];
    const float* coeff         = (const float*)d_in[2];
    const float* base_weight   = (const float*)d_in[3];
    const float* spline_weight = (const float*)d_in[4];
    float* out = (float*)d_out;

    prep_all_kernel<<<BATCH + 128 + 256, 256>>>(x, grid, coeff, base_weight,
                                                spline_weight, out);

    dim3 g(BATCH / BM, OUTF / BN, NSPLIT);
    gemm_kernel<<<g, 256>>>(out);
}